// round 1
// baseline (speedup 1.0000x reference)
#include <cuda_runtime.h>
#include <stdint.h>

// BasedKernel feature map, d=16:
//   out[row, 0]        = 1
//   out[row, 1..16]    = x[row, j-1] * 0.5           (1/sqrt(sqrt(16)) = 1/2)
//   out[row, 17..272]  = x[row,(t>>4)] * x[row,(t&15)] * 0.17677669529663687
//                        where t = j - 17  (1/(sqrt(2)*sqrt(16)))
//
// One warp per row. Lanes<16 load the row (coalesced), broadcast via shfl,
// each lane writes ~8.5 coalesced fp32 stores. Pure HBM-store-bound.

#define INV_RRD 0.5f
#define SC2     0.17677669529663687f  // 1/(sqrt(2)*4)

__global__ void __launch_bounds__(256, 8)
based_feature_kernel(const float* __restrict__ x,
                     float* __restrict__ out,
                     int n_rows)
{
    const int warp_global = (blockIdx.x * blockDim.x + threadIdx.x) >> 5;
    const int lane = threadIdx.x & 31;
    if (warp_global >= n_rows) return;

    // Load the 16-element row cooperatively (lanes 0..15), broadcast to all.
    const float* xr = x + (size_t)warp_global * 16;
    float v = (lane < 16) ? __ldg(xr + lane) : 0.0f;

    float xv[16];
#pragma unroll
    for (int i = 0; i < 16; ++i)
        xv[i] = __shfl_sync(0xffffffffu, v, i);

    float* o = out + (size_t)warp_global * 273;

    // ---- j = lane (0..31): mixed region ----
    {
        float val;
        if (lane == 0) {
            val = 1.0f;
        } else if (lane < 17) {
            val = xv[lane - 1] * INV_RRD;
        } else {
            const int t = lane - 17;          // 0..14 -> i = 0, k = t
            val = xv[0] * xv[t & 15] * SC2;
        }
        o[lane] = val;
    }

    // ---- j = lane + 32*k, k = 1..7: pure quadratic region (j in 32..255) ----
#pragma unroll
    for (int k = 1; k < 8; ++k) {
        const int j = lane + 32 * k;
        const int t = j - 17;                 // 15..238
        o[j] = xv[t >> 4] * xv[t & 15] * SC2;
    }

    // ---- tail: j = lane + 256, valid for lane < 17 (j in 256..272) ----
    if (lane < 17) {
        const int j = lane + 256;
        const int t = j - 17;                 // 239..255
        o[j] = xv[t >> 4] * xv[t & 15] * SC2;
    }
}

extern "C" void kernel_launch(void* const* d_in, const int* in_sizes, int n_in,
                              void* d_out, int out_size)
{
    const float* x = (const float*)d_in[0];
    float* out = (float*)d_out;

    const int n_rows = in_sizes[0] / 16;      // 4*16*4096 = 262144

    const int threads = 256;                  // 8 warps -> 8 rows per block
    const int rows_per_block = threads / 32;
    const int blocks = (n_rows + rows_per_block - 1) / rows_per_block;

    based_feature_kernel<<<blocks, threads>>>(x, out, n_rows);
}

// round 2
// speedup vs baseline: 1.6215x; 1.6215x over previous
#include <cuda_runtime.h>
#include <stdint.h>

// BasedKernel feature map, d=16:
//   out[row, 0]        = 1
//   out[row, 1..16]    = x[row, j-1] * 0.5
//   out[row, 17..272]  = x[row, t>>4] * x[row, t&15] * (1/(sqrt(2)*4)),  t = j-17
//
// R2: smem staging. Phase 1 computes rows into smem (conflict-free STS.32);
// phase 2 streams 8 rows = 546 aligned float4 to GMEM (STG.128, line-aligned).
// Removes the 1092B-stride misalignment that made R1 L1tex-bound (86.8%).

#define INV_RRD 0.5f
#define SC2     0.17677669529663687f

#define ROWS_PER_BLOCK 8
#define THREADS        256
#define FLOATS_PER_BLOCK (ROWS_PER_BLOCK * 273)      // 2184
#define VEC4_PER_BLOCK   (FLOATS_PER_BLOCK / 4)      // 546

__global__ void __launch_bounds__(THREADS, 8)
based_feature_kernel(const float* __restrict__ x,
                     float* __restrict__ out)
{
    __shared__ float buf[FLOATS_PER_BLOCK];

    const int tid  = threadIdx.x;
    const int warp = tid >> 5;                 // 0..7 = local row
    const int lane = tid & 31;
    const int row  = blockIdx.x * ROWS_PER_BLOCK + warp;

    // ---- Phase 1: compute one row per warp into smem ----
    const float* xr = x + (size_t)row * 16;
    float v = (lane < 16) ? __ldg(xr + lane) : 0.0f;

    float xv[16];
#pragma unroll
    for (int i = 0; i < 16; ++i)
        xv[i] = __shfl_sync(0xffffffffu, v, i);

    float* o = buf + warp * 273;

    {
        float val;
        if (lane == 0) {
            val = 1.0f;
        } else if (lane < 17) {
            val = xv[lane - 1] * INV_RRD;
        } else {
            const int t = lane - 17;           // 0..14 -> i=0, k=t
            val = xv[0] * xv[t & 15] * SC2;
        }
        o[lane] = val;
    }

#pragma unroll
    for (int k = 1; k < 8; ++k) {
        const int j = lane + 32 * k;
        const int t = j - 17;                  // 15..238
        o[j] = xv[t >> 4] * xv[t & 15] * SC2;
    }

    if (lane < 17) {
        const int j = lane + 256;
        const int t = j - 17;                  // 239..255
        o[j] = xv[t >> 4] * xv[t & 15] * SC2;
    }

    __syncthreads();

    // ---- Phase 2: aligned vectorized flush, 546 float4 per block ----
    // Block base byte = blockIdx * 8736, 8736 % 16 == 0 -> float4-aligned.
    const float4* s4 = reinterpret_cast<const float4*>(buf);
    float4* g4 = reinterpret_cast<float4*>(out + (size_t)blockIdx.x * FLOATS_PER_BLOCK);

#pragma unroll
    for (int i = tid; i < VEC4_PER_BLOCK; i += THREADS)
        g4[i] = s4[i];
}

extern "C" void kernel_launch(void* const* d_in, const int* in_sizes, int n_in,
                              void* d_out, int out_size)
{
    const float* x = (const float*)d_in[0];
    float* out = (float*)d_out;

    const int n_rows = in_sizes[0] / 16;              // 262144
    const int blocks = n_rows / ROWS_PER_BLOCK;       // 32768 (divides exactly)

    based_feature_kernel<<<blocks, THREADS>>>(x, out);
}

// round 3
// speedup vs baseline: 1.6339x; 1.0076x over previous
#include <cuda_runtime.h>
#include <stdint.h>

// BasedKernel feature map, d=16:
//   out[row, 0]        = 1
//   out[row, 1..16]    = x[row, j-1] * 0.5
//   out[row, 17..272]  = x[row, t>>4] * x[row, t&15] * (1/(sqrt(2)*4)),  t = j-17
//
// R3: phase 1 computes rows into smem (conflict-free contiguous STS.32);
// flush via ONE 1-D TMA bulk store (cp.async.bulk shared::cta -> global)
// per block: no LDS, no STG, no L1 wavefronts on the 286MB output stream.

#define INV_RRD 0.5f
#define SC2     0.17677669529663687f

#define ROWS_PER_BLOCK 8
#define THREADS        256
#define FLOATS_PER_BLOCK (ROWS_PER_BLOCK * 273)      // 2184
#define BYTES_PER_BLOCK  (FLOATS_PER_BLOCK * 4)      // 8736, multiple of 16

__global__ void __launch_bounds__(THREADS, 8)
based_feature_kernel(const float* __restrict__ x,
                     float* __restrict__ out)
{
    __shared__ __align__(16) float buf[FLOATS_PER_BLOCK];

    const int tid  = threadIdx.x;
    const int warp = tid >> 5;                 // 0..7 = local row
    const int lane = tid & 31;
    const int row  = blockIdx.x * ROWS_PER_BLOCK + warp;

    // ---- Phase 1: compute one row per warp into smem ----
    const float* xr = x + (size_t)row * 16;
    float v = (lane < 16) ? __ldg(xr + lane) : 0.0f;

    float xv[16];
#pragma unroll
    for (int i = 0; i < 16; ++i)
        xv[i] = __shfl_sync(0xffffffffu, v, i);

    float* o = buf + warp * 273;

    {
        float val;
        if (lane == 0) {
            val = 1.0f;
        } else if (lane < 17) {
            val = xv[lane - 1] * INV_RRD;
        } else {
            const int t = lane - 17;           // 0..14 -> i=0, k=t
            val = xv[0] * xv[t & 15] * SC2;
        }
        o[lane] = val;
    }

#pragma unroll
    for (int k = 1; k < 8; ++k) {
        const int j = lane + 32 * k;
        const int t = j - 17;                  // 15..238
        o[j] = xv[t >> 4] * xv[t & 15] * SC2;
    }

    if (lane < 17) {
        const int j = lane + 256;
        const int t = j - 17;                  // 239..255
        o[j] = xv[t >> 4] * xv[t & 15] * SC2;
    }

    __syncthreads();

    // ---- Phase 2: single 1-D TMA bulk store smem -> gmem (bypasses L1) ----
    if (tid == 0) {
        uint32_t saddr;
        asm volatile(
            "{ .reg .u64 t; cvta.to.shared.u64 t, %1; cvt.u32.u64 %0, t; }"
            : "=r"(saddr) : "l"(buf));

        float* g = out + (size_t)blockIdx.x * FLOATS_PER_BLOCK;
        const int nbytes = BYTES_PER_BLOCK;

        // Order generic-proxy smem writes before the async-proxy read.
        asm volatile("fence.proxy.async.shared::cta;" ::: "memory");
        asm volatile(
            "cp.async.bulk.global.shared::cta.bulk_group [%0], [%1], %2;"
            :: "l"(g), "r"(saddr), "r"(nbytes) : "memory");
        asm volatile("cp.async.bulk.commit_group;" ::: "memory");
        // Keep the CTA (and its smem) alive until the bulk read completes.
        asm volatile("cp.async.bulk.wait_group.read 0;" ::: "memory");
    }
}

extern "C" void kernel_launch(void* const* d_in, const int* in_sizes, int n_in,
                              void* d_out, int out_size)
{
    const float* x = (const float*)d_in[0];
    float* out = (float*)d_out;

    const int n_rows = in_sizes[0] / 16;              // 262144
    const int blocks = n_rows / ROWS_PER_BLOCK;       // 32768 (divides exactly)

    based_feature_kernel<<<blocks, THREADS>>>(x, out);
}

// round 4
// speedup vs baseline: 3.2972x; 2.0180x over previous
#include <cuda_runtime.h>
#include <stdint.h>

// BasedKernel feature map, d=16:
//   out[row, 0]        = 1
//   out[row, 1..16]    = x[row, j-1] * 0.5
//   out[row, 17+idx]   = x[row, idx>>4] * x[row, idx&15] * SC2,  idx = 0..255
//
// R4: no dynamically-indexed local array (R1-R3 secretly used local memory:
// LDL/STL through l1tex was the 84% ceiling). x stays one-value-per-lane;
// quadratic indices decompose as idx = 32m + lane -> i = 2m + (lane>>4),
// k = lane&15. k-operand is loop-invariant (1 hoisted shfl, premultiplied by
// SC2); i-operand is 1 dynamic-source shfl per iteration. 9 SHFL + 10 STS +
// 9 FMUL per row, then one TMA bulk store per block (L1-free flush).

#define SC2 0.17677669529663687f

#define ROWS_PER_BLOCK 8
#define THREADS        256
#define FLOATS_PER_BLOCK (ROWS_PER_BLOCK * 273)      // 2184
#define BYTES_PER_BLOCK  (FLOATS_PER_BLOCK * 4)      // 8736, multiple of 16

__global__ void __launch_bounds__(THREADS, 8)
based_feature_kernel(const float* __restrict__ x,
                     float* __restrict__ out)
{
    __shared__ __align__(16) float buf[FLOATS_PER_BLOCK];

    const int tid  = threadIdx.x;
    const int warp = tid >> 5;                 // 0..7 = local row
    const int lane = tid & 31;
    const int row  = blockIdx.x * ROWS_PER_BLOCK + warp;

    // ---- Phase 1: one row per warp, x resident one-value-per-lane ----
    const float* xr = x + (size_t)row * 16;
    float v = (lane < 16) ? __ldg(xr + lane) : 0.0f;

    float* o = buf + warp * 273;

    // Linear part + leading 1.
    if (lane < 16) o[1 + lane] = v * 0.5f;
    if (lane == 16) o[0] = 1.0f;

    // Loop-invariant k-operand: k = lane & 15, premultiplied by SC2.
    const float b2 = __shfl_sync(0xffffffffu, v, lane & 15) * SC2;
    const int   hi = lane >> 4;                // 0 or 1

    // Quadratic part: idx = 32m + lane, i = 2m + hi.
#pragma unroll
    for (int m = 0; m < 8; ++m) {
        const float a = __shfl_sync(0xffffffffu, v, 2 * m + hi);
        o[17 + 32 * m + lane] = a * b2;
    }

    __syncthreads();

    // ---- Phase 2: single 1-D TMA bulk store smem -> gmem (bypasses L1) ----
    if (tid == 0) {
        uint32_t saddr;
        asm volatile(
            "{ .reg .u64 t; cvta.to.shared.u64 t, %1; cvt.u32.u64 %0, t; }"
            : "=r"(saddr) : "l"(buf));

        float* g = out + (size_t)blockIdx.x * FLOATS_PER_BLOCK;
        const int nbytes = BYTES_PER_BLOCK;

        asm volatile("fence.proxy.async.shared::cta;" ::: "memory");
        asm volatile(
            "cp.async.bulk.global.shared::cta.bulk_group [%0], [%1], %2;"
            :: "l"(g), "r"(saddr), "r"(nbytes) : "memory");
        asm volatile("cp.async.bulk.commit_group;" ::: "memory");
        asm volatile("cp.async.bulk.wait_group.read 0;" ::: "memory");
    }
}

extern "C" void kernel_launch(void* const* d_in, const int* in_sizes, int n_in,
                              void* d_out, int out_size)
{
    const float* x = (const float*)d_in[0];
    float* out = (float*)d_out;

    const int n_rows = in_sizes[0] / 16;              // 262144
    const int blocks = n_rows / ROWS_PER_BLOCK;       // 32768

    based_feature_kernel<<<blocks, THREADS>>>(x, out);
}